// round 4
// baseline (speedup 1.0000x reference)
#include <cuda_runtime.h>
#include <cstdint>
#include <cstddef>

#define N_NODES   25
#define K_TOT     384
#define OUT_F     256
#define M_TOT     (8192 * N_NODES)
#define NEG_BIG   (-9e15f)
#define MAXNB     24
#define NCHUNK    12

// ---- shared memory layout ----
#define OFF_RAW   0               // 128 rows x 32 f (row stride 128B)   16 KB
#define OFF_A0    16384           // 128 rows x 20 float2 (160B stride)  20 KB
#define OFF_AZ    36864           // 20 KB
#define OFF_B     57344           // [2 buf][2 half][256 n][20 float2]  160 KB
#define B_BUF_SZ  81920
#define B_HALF_SZ 40960
#define OFF_META  221184
#define MT_BIAS   0               // 256 f
#define MT_DIAG   1024            // 25 f
#define MT_NNZ    1152            // 25 i
#define MT_SRC    1280            // 600 i
#define MT_COEF   3680            // 600 f
#define DSMEM     (OFF_META + 6144)   // 227328 B

__device__ float g_WTp[2 * OUT_F * K_TOT];  // [half][n][paired k], rna-rounded
__device__ float g_diag[N_NODES];
__device__ int   g_nnzc[N_NODES];
__device__ int   g_src[N_NODES * MAXNB];
__device__ float g_coef[N_NODES * MAXNB];

// ---------------- helpers ----------------
__device__ __forceinline__ float rna_tf32(float x) {
    uint32_t u; asm("cvt.rna.tf32.f32 %0, %1;" : "=r"(u) : "f"(x));
    return __uint_as_float(u);
}
__device__ __forceinline__ void cpa16(void* dst, const float* src) {
    uint32_t d = (uint32_t)__cvta_generic_to_shared(dst);
    asm volatile("cp.async.cg.shared.global [%0], [%1], 16;" :: "r"(d), "l"(src));
}
__device__ __forceinline__ void mma8(float c[4], float2 alo, float2 ahi, float2 b) {
    asm volatile(
        "mma.sync.aligned.m16n8k8.row.col.f32.tf32.tf32.f32 "
        "{%0,%1,%2,%3}, {%4,%5,%6,%7}, {%8,%9}, {%0,%1,%2,%3};\n"
        : "+f"(c[0]), "+f"(c[1]), "+f"(c[2]), "+f"(c[3])
        : "r"(__float_as_uint(alo.x)), "r"(__float_as_uint(ahi.x)),
          "r"(__float_as_uint(alo.y)), "r"(__float_as_uint(ahi.y)),
          "r"(__float_as_uint(b.x)),  "r"(__float_as_uint(b.y)));
}

// ================= setup: softmax -> diag/sparse lists; W^T paired rna ===
__global__ void setup_kernel(const float* __restrict__ W,
                             const float* __restrict__ e,
                             const int*   __restrict__ rows,
                             const int*   __restrict__ cols,
                             int nnz) {
    // g_WTp[h][n][pos], pos = chunk*32 + g*8 + lc*2 + h4  holds
    //   rna(W[h][k][n]) with k = chunk*32 + g*8 + h4*4 + lc
    const int total = 2 * OUT_F * K_TOT;
    for (int i = blockIdx.x * blockDim.x + threadIdx.x; i < total;
         i += gridDim.x * blockDim.x) {
        int h   = i / (OUT_F * K_TOT);
        int rem = i - h * (OUT_F * K_TOT);
        int n   = rem / K_TOT;
        int pos = rem - n * K_TOT;
        int chunk = pos >> 5, r5 = pos & 31;
        int g = r5 >> 3, q = r5 & 7;
        int lc = q >> 1, h4 = q & 1;
        int k = chunk * 32 + g * 8 + h4 * 4 + lc;
        g_WTp[i] = rna_tf32(W[h * (K_TOT * OUT_F) + k * OUT_F + n]);
    }
    if (blockIdx.x == 0) {
        __shared__ float lg[N_NODES * N_NODES];
        int t = threadIdx.x;
        for (int i = t; i < N_NODES * N_NODES; i += blockDim.x) lg[i] = NEG_BIG;
        __syncthreads();
        for (int i = t; i < nnz; i += blockDim.x) lg[rows[i] * N_NODES + cols[i]] = e[i];
        __syncthreads();
        if (t < N_NODES) {
            float mx = -1e30f;
            #pragma unroll
            for (int n = 0; n < N_NODES; n++) mx = fmaxf(mx, lg[t * N_NODES + n]);
            float ex[N_NODES]; float s = 0.f;
            #pragma unroll
            for (int n = 0; n < N_NODES; n++) {
                ex[n] = expf(lg[t * N_NODES + n] - mx); s += ex[n];
            }
            float inv = 1.f / s;
            int cnt = 0;
            for (int n = 0; n < N_NODES; n++) {
                float a = ex[n] * inv;
                if (n == t) g_diag[t] = a;
                else if (lg[t * N_NODES + n] != NEG_BIG) {
                    g_src[t * MAXNB + cnt] = n;
                    g_coef[t * MAXNB + cnt] = a;
                    cnt++;
                }
            }
            g_nnzc[t] = cnt;
        }
    }
}

// ================= fused premix + tf32 GEMM ===============================
__global__ void __launch_bounds__(256, 1)
fused_kernel(const float* __restrict__ nodev, const float* __restrict__ hid,
             const float* __restrict__ bias, float* __restrict__ out) {
    extern __shared__ char sm[];
    const int tid = threadIdx.x, wid = tid >> 5, lid = tid & 31;
    const int lr = lid >> 2, lc = lid & 3;
    const int wm = wid >> 2, wn = wid & 3;       // 2 x 4 warp grid
    const int row0  = blockIdx.x * 125;
    const int nrows = (M_TOT - row0 < 125) ? (M_TOT - row0) : 125;

    float*  rawf   = (float*)(sm + OFF_RAW);
    float2* A0s    = (float2*)(sm + OFF_A0);
    float2* AZs    = (float2*)(sm + OFF_AZ);
    float*  s_bias = (float*)(sm + OFF_META + MT_BIAS);
    float*  s_diag = (float*)(sm + OFF_META + MT_DIAG);
    int*    s_nnz  = (int*)  (sm + OFF_META + MT_NNZ);
    int*    s_src  = (int*)  (sm + OFF_META + MT_SRC);
    float*  s_coef = (float*)(sm + OFF_META + MT_COEF);

    for (int i = tid; i < 256; i += 256) s_bias[i] = bias[i];
    if (tid < N_NODES) { s_diag[tid] = g_diag[tid]; s_nnz[tid] = g_nnzc[tid]; }
    for (int i = tid; i < N_NODES * MAXNB; i += 256) {
        s_src[i] = g_src[i]; s_coef[i] = g_coef[i];
    }

    // ---- loader lambdas ----
    auto fill_raw = [&](int s) {
        const int k0 = s * 32;
        #pragma unroll
        for (int i = 0; i < 4; i++) {
            int idx = i * 256 + tid;
            int row = idx >> 3, j = idx & 7;
            int grow = row0 + row; if (grow > M_TOT - 1) grow = M_TOT - 1;
            const float* src = (k0 < 128)
                ? (nodev + (size_t)grow * 128 + k0 + j * 4)
                : (hid   + (size_t)grow * 256 + (k0 - 128) + j * 4);
            cpa16(sm + OFF_RAW + row * 128 + j * 16, src);
        }
    };
    auto fill_B = [&](int s, int buf) {
        #pragma unroll
        for (int i = 0; i < 16; i++) {
            int idx = i * 256 + tid;            // 4096 segments of 16B
            int h = idx >> 11, n = (idx >> 3) & 255, j = idx & 7;
            cpa16(sm + OFF_B + buf * B_BUF_SZ + h * B_HALF_SZ + n * 160 + j * 16,
                  g_WTp + ((h << 8) + n) * (size_t)K_TOT + s * 32 + j * 4);
        }
    };

    fill_raw(0);
    fill_B(0, 0);
    asm volatile("cp.async.commit_group;");

    float acc[4][8][4];
    #pragma unroll
    for (int a = 0; a < 4; a++)
        #pragma unroll
        for (int b = 0; b < 8; b++)
            #pragma unroll
            for (int c = 0; c < 4; c++) acc[a][b][c] = 0.f;

    const int rb = wm * 64;
    const int g_idx = lid >> 3, kq = lid & 7;    // premix write slot
    const int p_lc = kq & 3, p_h = kq >> 2;

    #pragma unroll 1
    for (int s = 0; s < NCHUNK; s++) {
        const int buf = s & 1;
        asm volatile("cp.async.wait_group 0;");
        __syncthreads();

        // ---- premix: each warp 16 rows, lane = k within chunk ----
        {
            const int m0 = wid * 16;
            #pragma unroll 2
            for (int r = 0; r < 16; r++) {
                int m = m0 + r;
                int bl = m / N_NODES; if (bl > 4) bl = 4;
                int node = m - bl * N_NODES; if (node > 24) node = 24;
                int base = bl * N_NODES;
                float x  = rawf[m * 32 + lid];
                float a0 = s_diag[node] * x;
                float z  = 0.f;
                int nn = s_nnz[node];
                const int*   sp = s_src  + node * MAXNB;
                const float* cp = s_coef + node * MAXNB;
                #pragma unroll 4
                for (int j = 0; j < nn; j++)
                    z += cp[j] * rawf[(base + sp[j]) * 32 + lid];
                int fo = m * 40 + g_idx * 8 + p_lc * 2 + p_h;
                ((float*)A0s)[fo] = rna_tf32(a0);
                ((float*)AZs)[fo] = rna_tf32(z);
            }
        }
        __syncthreads();   // A tiles ready; raw buffer free

        if (s + 1 < NCHUNK) {
            fill_raw(s + 1);
            fill_B(s + 1, buf ^ 1);
            asm volatile("cp.async.commit_group;");
        }

        // ---- compute: two passes (A0@W0, AZ@W1) ----
        #pragma unroll
        for (int pass = 0; pass < 2; pass++) {
            const float2* As = pass ? AZs : A0s;
            const float2* Bs = (const float2*)(sm + OFF_B + buf * B_BUF_SZ
                                               + pass * B_HALF_SZ);
            #pragma unroll
            for (int ks = 0; ks < 4; ks++) {
                float2 alo[4], ahi[4];
                #pragma unroll
                for (int mf = 0; mf < 4; mf++) {
                    alo[mf] = As[(rb + mf * 16 + lr)     * 20 + ks * 4 + lc];
                    ahi[mf] = As[(rb + mf * 16 + lr + 8) * 20 + ks * 4 + lc];
                }
                #pragma unroll
                for (int nf = 0; nf < 8; nf++) {
                    float2 b = Bs[(wn * 64 + nf * 8 + lr) * 20 + ks * 4 + lc];
                    #pragma unroll
                    for (int mf = 0; mf < 4; mf++)
                        mma8(acc[mf][nf], alo[mf], ahi[mf], b);
                }
            }
        }
    }

    // ---- epilogue: acc + bias -> out ----
    const float2* bias2 = (const float2*)s_bias;
    #pragma unroll
    for (int mf = 0; mf < 4; mf++) {
        const int ml0 = rb + mf * 16 + lr;
        const bool v0 = ml0 < nrows, v1 = ml0 + 8 < nrows;
        float* o0 = out + ((size_t)row0 + ml0)     * OUT_F;
        float* o1 = out + ((size_t)row0 + ml0 + 8) * OUT_F;
        #pragma unroll
        for (int nf = 0; nf < 8; nf++) {
            const int col = wn * 64 + nf * 8 + lc * 2;
            float2 bv = bias2[col >> 1];
            if (v0) *(float2*)(o0 + col) =
                make_float2(acc[mf][nf][0] + bv.x, acc[mf][nf][1] + bv.y);
            if (v1) *(float2*)(o1 + col) =
                make_float2(acc[mf][nf][2] + bv.x, acc[mf][nf][3] + bv.y);
        }
    }
}

// ================= launcher ==============================================
extern "C" void kernel_launch(void* const* d_in, const int* in_sizes, int n_in,
                              void* d_out, int out_size) {
    const float* nodev = (const float*)d_in[0];
    const float* hid   = (const float*)d_in[1];
    const float* W     = (const float*)d_in[2];
    const float* e     = (const float*)d_in[3];
    const float* bias  = (const float*)d_in[4];
    const int*   rows  = (const int*)d_in[5];
    const int*   cols  = (const int*)d_in[6];
    const int nnz = in_sizes[3];

    setup_kernel<<<64, 256>>>(W, e, rows, cols, nnz);

    cudaFuncSetAttribute(fused_kernel,
                         cudaFuncAttributeMaxDynamicSharedMemorySize, DSMEM);
    const int grid = (M_TOT + 124) / 125;   // 1639
    fused_kernel<<<grid, 256, DSMEM>>>(nodev, hid, bias, (float*)d_out);
    (void)n_in; (void)out_size;
}